// round 10
// baseline (speedup 1.0000x reference)
#include <cuda_runtime.h>
#include <math.h>

#define T_LEN 512
#define B_SZ  64
#define D_SZ  1024
#define H_SZ  512
#define L_SZ  5

#define NCTA 128
#define NTHR 256

// dynamic smem: h_s 4*32*64 f (32KB) + w_s 2*512*4 f (16KB) + pr 4*2*4*64 f (8KB)
#define SM_HS 0
#define SM_WS (4 * 32 * 64)
#define SM_PR (SM_WS + 2 * 512 * 4)
#define SM_FLOATS (SM_PR + 4 * 2 * 4 * 64)
#define SMEM_TOT (SM_FLOATS * 4)

// ---------------- device-global scratch ----------------------------------------
__device__ float    g_XHt[T_LEN * H_SZ * B_SZ];   // [t][j][b]
__device__ float    g_XCt[T_LEN * H_SZ * B_SZ];   // [t][j][b]
__device__ float    g_h[2][H_SZ * B_SZ];          // hidden double buffer [j][b]
__device__ unsigned g_grpc[8 * 64];               // 8 group counters, 256B apart
__device__ unsigned g_rootc;
__device__ unsigned g_rel2;

// Two-level ticket barrier, R2-proven mechanics (atomicAdd/atomicExch/volatile
// poll/threadfence). ALL generations self-derived from tickets => monotonic,
// graph-replay safe. Group: 16 arrivals on g_grpc[cta&7]; root: 8 arrivals.
__device__ __forceinline__ void gbar(int tid, int cta) {
    __syncthreads();
    if (tid == 0) {
        __threadfence();
        unsigned t0 = atomicAdd(&g_grpc[(cta & 7) * 64], 1u);
        unsigned gen = (t0 >> 4) + 1u;            // 16 arrivals per group
        if ((t0 & 15u) == 15u) {
            unsigned t1 = atomicAdd(&g_rootc, 1u);
            if ((t1 & 7u) == 7u) {
                atomicExch(&g_rel2, (t1 >> 3) + 1u);
            }
        }
        while ((int)(*(volatile unsigned*)&g_rel2 - gen) < 0) { }
        __threadfence();
    }
    __syncthreads();
}

// ---------------- precompute: XHt/XCt[t][j][b] = x[t,b,:]@W[:,j] + bias[j] ------
__global__ void __launch_bounds__(NTHR) proj_kernel(
    const float* __restrict__ x,
    const float* __restrict__ Ww,
    const float* __restrict__ Wb,
    const int gate)
{
    __shared__ float As[32][128];
    __shared__ float Bs[32][64];
    float* __restrict__ dst = gate ? g_XCt : g_XHt;

    const int tid = threadIdx.x;
    const int bm  = blockIdx.x * 128;
    const int bn  = blockIdx.y * 64;
    const int tm  = tid & 15;
    const int tn  = tid >> 4;

    float acc[8][4];
#pragma unroll
    for (int i = 0; i < 8; i++)
#pragma unroll
        for (int j = 0; j < 4; j++) acc[i][j] = 0.0f;

    for (int k0 = 0; k0 < D_SZ; k0 += 32) {
#pragma unroll
        for (int r = 0; r < 4; r++) {
            int lin = tid + r * 256;
            int m = lin >> 3, kq = lin & 7;
            float4 v = *(const float4*)(x + (size_t)(bm + m) * D_SZ + k0 + kq * 4);
            As[kq * 4 + 0][m] = v.x;
            As[kq * 4 + 1][m] = v.y;
            As[kq * 4 + 2][m] = v.z;
            As[kq * 4 + 3][m] = v.w;
        }
#pragma unroll
        for (int r = 0; r < 2; r++) {
            int lin = tid + r * 256;
            int kk = lin >> 4, jq = lin & 15;
            *(float4*)&Bs[kk][jq * 4] =
                *(const float4*)(Ww + (size_t)(k0 + kk) * H_SZ + bn + jq * 4);
        }
        __syncthreads();
#pragma unroll
        for (int k = 0; k < 32; k++) {
            float4 a0 = *(const float4*)&As[k][tm * 4];
            float4 a1 = *(const float4*)&As[k][64 + tm * 4];
            float4 bv = *(const float4*)&Bs[k][tn * 4];
            float av[8] = {a0.x, a0.y, a0.z, a0.w, a1.x, a1.y, a1.z, a1.w};
            float bw[4] = {bv.x, bv.y, bv.z, bv.w};
#pragma unroll
            for (int i = 0; i < 8; i++)
#pragma unroll
                for (int j = 0; j < 4; j++)
                    acc[i][j] = fmaf(av[i], bw[j], acc[i][j]);
        }
        __syncthreads();
    }

#pragma unroll
    for (int i = 0; i < 8; i++) {
        int m = bm + ((i < 4) ? (tm * 4 + i) : (64 + tm * 4 + i - 4));
        int t = m >> 6, b = m & 63;
#pragma unroll
        for (int j = 0; j < 4; j++) {
            int jj = bn + tn * 4 + j;
            dst[(size_t)t * (H_SZ * B_SZ) + (size_t)jj * B_SZ + b] = acc[i][j] + Wb[jj];
        }
    }
}

// ---------------- persistent sequential kernel: ONE barrier per layer -----------
// 128 CTAs, CTA = 4 j x 64 b x full K=512 x 2 gates. K split into 4 quarters
// across thread groups; in-CTA smem reduce; epilogue in-CTA; 1 grid barrier.
// Thread (kq,g,jj,bq): 8 b x 1 j x 1 gate over 128 k => per-k: 2 LDS.128 +
// 1 LDS.32 + 8 FFMA (FMA-pipe bound). Weights 16KB/CTA/layer (as R2).
__global__ void __launch_bounds__(NTHR, 1) rhn_seq_kernel(
    const float* __restrict__ RHw, const float* __restrict__ RHb,
    const float* __restrict__ RCw, const float* __restrict__ RCb,
    float* __restrict__ out)
{
    extern __shared__ __align__(16) float smem[];
    float* __restrict__ h_s = smem + SM_HS;   // [kq][32][64]
    float* __restrict__ w_s = smem + SM_WS;   // [g][512][4]
    float* __restrict__ pr  = smem + SM_PR;   // [(kq*2+g)*4+j][64]

    const int tid = threadIdx.x;
    const int cta = blockIdx.x;
    const int j0  = cta * 4;

    // compute mapping
    const int kq = tid >> 6;          // k quarter
    const int g  = (tid >> 5) & 1;    // gate
    const int jj = (tid >> 3) & 3;    // j within CTA
    const int bq = tid & 7;           // b octet (8 consecutive b)

    // epilogue mapping
    const int jl = tid >> 6;          // 0..3
    const int bl = tid & 63;

    // h0 = 0
    g_h[0][cta * NTHR + tid] = 0.0f;

    // biases constant across run
    float bHr[L_SZ], bCr[L_SZ];
#pragma unroll
    for (int l = 0; l < L_SZ; l++) {
        bHr[l] = RHb[l * H_SZ + j0 + jl];
        bCr[l] = RCb[l * H_SZ + j0 + jl];
    }

    gbar(tid, cta);

    int p = 0;
    for (int pass = 0; pass < 2; pass++)
    for (int t = 0; t < T_LEN; t++)
    for (int l = 0; l < L_SZ; l++) {
        const float* __restrict__ Rh = RHw + (size_t)l * H_SZ * H_SZ;
        const float* __restrict__ Rc = RCw + (size_t)l * H_SZ * H_SZ;
        const float* __restrict__ hp = g_h[p];

        // early prefetch of epilogue operands (hidden under phase A)
        float hold = hp[(j0 + jl) * B_SZ + bl];
        float xh = 0.0f, xc = 0.0f;
        if (l == 0) {
            xh = g_XHt[(size_t)t * (H_SZ * B_SZ) + (j0 + jl) * B_SZ + bl];
            xc = g_XCt[(size_t)t * (H_SZ * B_SZ) + (j0 + jl) * B_SZ + bl];
        }

        // ---- stage weights (16KB) + h chunk 0 ----
        float4 wv[4];
#pragma unroll
        for (int i = 0; i < 4; i++) {
            int item = tid + i * 256;
            int gw = item >> 9, kw = item & 511;
            const float* src = gw ? Rc : Rh;
            wv[i] = *(const float4*)(src + (size_t)kw * H_SZ + j0);
        }
        float4 hv[8];
#pragma unroll
        for (int i = 0; i < 8; i++) {
            int it = tid + i * 256;
            int q = it >> 9, r = it & 511;
            int row = r >> 4, col = r & 15;
            hv[i] = *(const float4*)(hp + ((q * 128 + row) << 6) + col * 4);
        }
#pragma unroll
        for (int i = 0; i < 4; i++) {
            int item = tid + i * 256;
            *(float4*)&w_s[item * 4] = wv[i];
        }
#pragma unroll
        for (int i = 0; i < 8; i++) {
            int it = tid + i * 256;
            int q = it >> 9, r = it & 511;
            *(float4*)&h_s[(q * 32 + (r >> 4)) * 64 + (r & 15) * 4] = hv[i];
        }
        __syncthreads();

        float4 a0 = make_float4(0.f, 0.f, 0.f, 0.f);
        float4 a1 = make_float4(0.f, 0.f, 0.f, 0.f);

#pragma unroll
        for (int c = 0; c < 4; c++) {
            if (c < 3) {
#pragma unroll
                for (int i = 0; i < 8; i++) {
                    int it = tid + i * 256;
                    int q = it >> 9, r = it & 511;
                    int row = r >> 4, col = r & 15;
                    hv[i] = *(const float4*)(hp +
                        ((q * 128 + (c + 1) * 32 + row) << 6) + col * 4);
                }
            }
            {
                const float* __restrict__ hq = h_s + kq * 2048 + bq * 8;
                const float* __restrict__ wq =
                    w_s + ((g * 512 + kq * 128 + c * 32) << 2) + jj;
#pragma unroll
                for (int kk = 0; kk < 32; kk++) {
                    float w = wq[kk * 4];
                    float4 x0 = *(const float4*)&hq[kk * 64];
                    float4 x1 = *(const float4*)&hq[kk * 64 + 4];
                    a0.x = fmaf(x0.x, w, a0.x); a0.y = fmaf(x0.y, w, a0.y);
                    a0.z = fmaf(x0.z, w, a0.z); a0.w = fmaf(x0.w, w, a0.w);
                    a1.x = fmaf(x1.x, w, a1.x); a1.y = fmaf(x1.y, w, a1.y);
                    a1.z = fmaf(x1.z, w, a1.z); a1.w = fmaf(x1.w, w, a1.w);
                }
            }
            if (c < 3) {
                __syncthreads();
#pragma unroll
                for (int i = 0; i < 8; i++) {
                    int it = tid + i * 256;
                    int q = it >> 9, r = it & 511;
                    *(float4*)&h_s[(q * 32 + (r >> 4)) * 64 + (r & 15) * 4] = hv[i];
                }
                __syncthreads();
            }
        }

        // ---- in-CTA reduce + epilogue ----
        {
            int prow = (kq * 2 + g) * 4 + jj;
            *(float4*)&pr[prow * 64 + bq * 8]     = a0;
            *(float4*)&pr[prow * 64 + bq * 8 + 4] = a1;
        }
        __syncthreads();
        {
            float sH = pr[((0 * 2 + 0) * 4 + jl) * 64 + bl]
                     + pr[((1 * 2 + 0) * 4 + jl) * 64 + bl]
                     + pr[((2 * 2 + 0) * 4 + jl) * 64 + bl]
                     + pr[((3 * 2 + 0) * 4 + jl) * 64 + bl];
            float sC = pr[((0 * 2 + 1) * 4 + jl) * 64 + bl]
                     + pr[((1 * 2 + 1) * 4 + jl) * 64 + bl]
                     + pr[((2 * 2 + 1) * 4 + jl) * 64 + bl]
                     + pr[((3 * 2 + 1) * 4 + jl) * 64 + bl];
            sH += bHr[l];
            sC += bCr[l];
            if (l == 0) { sH += xh; sC += xc; }
            float hl = 1.0f - 2.0f / (1.0f + __expf(2.0f * sH));   // tanh
            float tl = 1.0f / (1.0f + __expf(-sC));                // sigmoid
            float hn = fmaf(tl, hl - hold, hold);
            g_h[p ^ 1][(j0 + jl) * B_SZ + bl] = hn;
            if (l == L_SZ - 1) {
                size_t o = (size_t)t * (B_SZ * 2 * H_SZ) + (size_t)bl * (2 * H_SZ)
                         + (size_t)pass * H_SZ + j0 + jl;
                out[o] = hn;
                if (t == T_LEN - 1) {
                    out[(size_t)T_LEN * (B_SZ * 2 * H_SZ) + (size_t)bl * (2 * H_SZ)
                        + (size_t)pass * H_SZ + j0 + jl] = hn;
                }
            }
        }
        gbar(tid, cta);
        p ^= 1;
    }
}

extern "C" void kernel_launch(void* const* d_in, const int* in_sizes, int n_in,
                              void* d_out, int out_size)
{
    const float* x   = (const float*)d_in[0];
    const float* WHw = (const float*)d_in[1];
    const float* WHb = (const float*)d_in[2];
    const float* WCw = (const float*)d_in[3];
    const float* WCb = (const float*)d_in[4];
    const float* RHw = (const float*)d_in[5];
    const float* RHb = (const float*)d_in[6];
    const float* RCw = (const float*)d_in[7];
    const float* RCb = (const float*)d_in[8];
    float* out = (float*)d_out;

    cudaFuncSetAttribute(rhn_seq_kernel,
                         cudaFuncAttributeMaxDynamicSharedMemorySize, SMEM_TOT);

    dim3 pg(256, 8);
    proj_kernel<<<pg, NTHR>>>(x, WHw, WHb, 0);
    proj_kernel<<<pg, NTHR>>>(x, WCw, WCb, 1);
    rhn_seq_kernel<<<NCTA, NTHR, SMEM_TOT>>>(RHw, RHb, RCw, RCb, out);
}

// round 11
// speedup vs baseline: 1.6063x; 1.6063x over previous
#include <cuda_runtime.h>
#include <math.h>

#define T_LEN 512
#define B_SZ  64
#define D_SZ  1024
#define H_SZ  512
#define L_SZ  5

#define NCTA 128
#define NTHR 256

// ---------------- scratch (device globals: no allocation allowed) ----------------
__device__ float    g_XHt[T_LEN * H_SZ * B_SZ];   // [t][j][b]  x@W_H + b_H
__device__ float    g_XCt[T_LEN * H_SZ * B_SZ];   // [t][j][b]  x@W_C + b_C
__device__ float    g_h[2][H_SZ * B_SZ];          // hidden double buffer, [j][b]
__device__ float    g_part[2][4][H_SZ][B_SZ];     // K-split partials: [gate][kg][j][b]
__device__ unsigned g_grpc[8 * 64];               // 8 group counters, 256B apart
__device__ unsigned g_rootc;
__device__ unsigned g_rel2;

// ---------------- two-level ticket barrier (R2 mechanics, smaller drains) -------
// Level 1: 16 arrivals on g_grpc[cta&7] (8 counters in parallel).
// Level 2: 8 group-leaders on g_rootc; last sets g_rel2 via atomicExch.
// All generations self-derived from tickets -> monotonic, graph-replay safe.
// Fences + volatile poll exactly as the proven R2 barrier.
__device__ __forceinline__ void gbar(int tid, int cta) {
    __syncthreads();
    if (tid == 0) {
        __threadfence();
        unsigned t0 = atomicAdd(&g_grpc[(cta & 7) * 64], 1u);
        unsigned gen = (t0 >> 4) + 1u;            // 16 arrivals per group
        if ((t0 & 15u) == 15u) {
            unsigned t1 = atomicAdd(&g_rootc, 1u);
            if ((t1 & 7u) == 7u) {
                atomicExch(&g_rel2, (t1 >> 3) + 1u);
            }
        }
        while ((int)(*(volatile unsigned*)&g_rel2 - gen) < 0) { }
        __threadfence();
    }
    __syncthreads();
}

// ---------------- precompute: XHt/XCt[t][j][b] = x[t,b,:]@W[:,j] + bias[j] -------
__global__ void __launch_bounds__(NTHR) proj_kernel(
    const float* __restrict__ x,
    const float* __restrict__ Ww,
    const float* __restrict__ Wb,
    const int gate)
{
    __shared__ float As[32][128];
    __shared__ float Bs[32][64];
    float* __restrict__ dst = gate ? g_XCt : g_XHt;

    const int tid = threadIdx.x;
    const int bm  = blockIdx.x * 128;
    const int bn  = blockIdx.y * 64;
    const int tm  = tid & 15;
    const int tn  = tid >> 4;

    float acc[8][4];
#pragma unroll
    for (int i = 0; i < 8; i++)
#pragma unroll
        for (int j = 0; j < 4; j++) acc[i][j] = 0.0f;

    for (int k0 = 0; k0 < D_SZ; k0 += 32) {
#pragma unroll
        for (int r = 0; r < 4; r++) {
            int lin = tid + r * 256;
            int m = lin >> 3, kq = lin & 7;
            float4 v = *(const float4*)(x + (size_t)(bm + m) * D_SZ + k0 + kq * 4);
            As[kq * 4 + 0][m] = v.x;
            As[kq * 4 + 1][m] = v.y;
            As[kq * 4 + 2][m] = v.z;
            As[kq * 4 + 3][m] = v.w;
        }
#pragma unroll
        for (int r = 0; r < 2; r++) {
            int lin = tid + r * 256;
            int kk = lin >> 4, jq = lin & 15;
            *(float4*)&Bs[kk][jq * 4] =
                *(const float4*)(Ww + (size_t)(k0 + kk) * H_SZ + bn + jq * 4);
        }
        __syncthreads();
#pragma unroll
        for (int k = 0; k < 32; k++) {
            float4 a0 = *(const float4*)&As[k][tm * 4];
            float4 a1 = *(const float4*)&As[k][64 + tm * 4];
            float4 bv = *(const float4*)&Bs[k][tn * 4];
            float av[8] = {a0.x, a0.y, a0.z, a0.w, a1.x, a1.y, a1.z, a1.w};
            float bw[4] = {bv.x, bv.y, bv.z, bv.w};
#pragma unroll
            for (int i = 0; i < 8; i++)
#pragma unroll
                for (int j = 0; j < 4; j++)
                    acc[i][j] = fmaf(av[i], bw[j], acc[i][j]);
        }
        __syncthreads();
    }

#pragma unroll
    for (int i = 0; i < 8; i++) {
        int m = bm + ((i < 4) ? (tm * 4 + i) : (64 + tm * 4 + i - 4));
        int t = m >> 6, b = m & 63;
#pragma unroll
        for (int j = 0; j < 4; j++) {
            int jj = bn + tn * 4 + j;
            dst[(size_t)t * (H_SZ * B_SZ) + (size_t)jj * B_SZ + b] = acc[i][j] + Wb[jj];
        }
    }
}

// ---------------- persistent sequential kernel (R2 structure, verbatim) ----------
// Phase A: 128 CTAs = 32 j-groups x 4 k-groups; CTA tile = 64b x 16j x 128k x 2g.
//   Thread = 4b x 1j x 2 gates (8 fp32 accumulators). FMA-pipe bound.
// Phase B: 1 hidden element per thread: reduce 4 partials, bias (+X proj at l==0),
//   MUFU tanh/sigmoid, highway combine, write next hidden (+ outputs at l==L-1).
__global__ void __launch_bounds__(NTHR, 1) rhn_seq_kernel(
    const float* __restrict__ RHw, const float* __restrict__ RHb,
    const float* __restrict__ RCw, const float* __restrict__ RCb,
    float* __restrict__ out)
{
    const int tid = threadIdx.x;
    const int cta = blockIdx.x;

    __shared__ float hs[32][64];      // [k][b] chunk of hidden
    __shared__ float rhs_s[32][16];   // [k][j] chunk of R_H
    __shared__ float rcs_s[32][16];   // [k][j] chunk of R_C

    // h0 = 0
    g_h[0][cta * NTHR + tid] = 0.0f;

    const int jx  = tid & 15;         // j within 16-wide group
    const int byq = tid >> 4;         // b quad index (4 consecutive b)
    const int jg  = cta & 31;
    const int kg  = cta >> 5;
    const int j0  = jg * 16;
    const int k0  = kg * 128;

    const int kk_r = tid >> 3, jq_r = tid & 7;

    const int e   = cta * NTHR + tid; // phase-B element (0..32767)
    const int eb  = e & 63;
    const int ej  = e >> 6;

    // biases constant across the whole run
    float bHr[L_SZ], bCr[L_SZ];
#pragma unroll
    for (int l = 0; l < L_SZ; l++) {
        bHr[l] = RHb[l * H_SZ + ej];
        bCr[l] = RCb[l * H_SZ + ej];
    }

    gbar(tid, cta);

    int p = 0;
    for (int pass = 0; pass < 2; pass++)
    for (int t = 0; t < T_LEN; t++)
    for (int l = 0; l < L_SZ; l++) {
        const float* __restrict__ Rh = RHw + (size_t)l * H_SZ * H_SZ;
        const float* __restrict__ Rc = RCw + (size_t)l * H_SZ * H_SZ;
        const float* __restrict__ hp = g_h[p];

        float aH0 = 0, aH1 = 0, aH2 = 0, aH3 = 0;
        float aC0 = 0, aC1 = 0, aC2 = 0, aC3 = 0;

        // software-pipelined staging: prefetch chunk 0
        float4 h0v, h1v;
        float2 r0v, r1v;
        {
            const float4* h4 = (const float4*)(hp + k0 * 64);
            h0v = h4[tid];
            h1v = h4[tid + 256];
            r0v = *(const float2*)(Rh + (size_t)(k0 + kk_r) * H_SZ + j0 + 2 * jq_r);
            r1v = *(const float2*)(Rc + (size_t)(k0 + kk_r) * H_SZ + j0 + 2 * jq_r);
        }
#pragma unroll
        for (int c = 0; c < 4; c++) {
            __syncthreads();
            ((float4*)hs)[tid]       = h0v;
            ((float4*)hs)[tid + 256] = h1v;
            ((float2*)rhs_s)[tid]    = r0v;
            ((float2*)rcs_s)[tid]    = r1v;
            __syncthreads();
            if (c < 3) {
                int kb = k0 + (c + 1) * 32;
                const float4* h4 = (const float4*)(hp + kb * 64);
                h0v = h4[tid];
                h1v = h4[tid + 256];
                r0v = *(const float2*)(Rh + (size_t)(kb + kk_r) * H_SZ + j0 + 2 * jq_r);
                r1v = *(const float2*)(Rc + (size_t)(kb + kk_r) * H_SZ + j0 + 2 * jq_r);
            }
#pragma unroll
            for (int kk = 0; kk < 32; kk++) {
                float rh = rhs_s[kk][jx];
                float rc = rcs_s[kk][jx];
                float4 hv = *(const float4*)&hs[kk][byq * 4];
                aH0 = fmaf(hv.x, rh, aH0); aH1 = fmaf(hv.y, rh, aH1);
                aH2 = fmaf(hv.z, rh, aH2); aH3 = fmaf(hv.w, rh, aH3);
                aC0 = fmaf(hv.x, rc, aC0); aC1 = fmaf(hv.y, rc, aC1);
                aC2 = fmaf(hv.z, rc, aC2); aC3 = fmaf(hv.w, rc, aC3);
            }
        }
        *(float4*)&g_part[0][kg][j0 + jx][byq * 4] = make_float4(aH0, aH1, aH2, aH3);
        *(float4*)&g_part[1][kg][j0 + jx][byq * 4] = make_float4(aC0, aC1, aC2, aC3);
        gbar(tid, cta);

        // ---- phase B: reduce + activations + highway combine ----
        {
            float sH = g_part[0][0][ej][eb] + g_part[0][1][ej][eb]
                     + g_part[0][2][ej][eb] + g_part[0][3][ej][eb];
            float sC = g_part[1][0][ej][eb] + g_part[1][1][ej][eb]
                     + g_part[1][2][ej][eb] + g_part[1][3][ej][eb];
            sH += bHr[l];
            sC += bCr[l];
            if (l == 0) {
                sH += g_XHt[(size_t)t * (H_SZ * B_SZ) + e];
                sC += g_XCt[(size_t)t * (H_SZ * B_SZ) + e];
            }
            float hold = g_h[p][e];
            float hl = 1.0f - 2.0f / (1.0f + __expf(2.0f * sH));   // tanh
            float tl = 1.0f / (1.0f + __expf(-sC));                // sigmoid
            float hn = fmaf(tl, hl - hold, hold);
            g_h[p ^ 1][e] = hn;
            if (l == L_SZ - 1) {
                size_t o = (size_t)t * (B_SZ * 2 * H_SZ) + (size_t)eb * (2 * H_SZ)
                         + (size_t)pass * H_SZ + ej;
                out[o] = hn;
                if (t == T_LEN - 1) {
                    out[(size_t)T_LEN * (B_SZ * 2 * H_SZ) + (size_t)eb * (2 * H_SZ)
                        + (size_t)pass * H_SZ + ej] = hn;
                }
            }
        }
        gbar(tid, cta);
        p ^= 1;
    }
}

extern "C" void kernel_launch(void* const* d_in, const int* in_sizes, int n_in,
                              void* d_out, int out_size)
{
    const float* x   = (const float*)d_in[0];
    const float* WHw = (const float*)d_in[1];
    const float* WHb = (const float*)d_in[2];
    const float* WCw = (const float*)d_in[3];
    const float* WCb = (const float*)d_in[4];
    const float* RHw = (const float*)d_in[5];
    const float* RHb = (const float*)d_in[6];
    const float* RCw = (const float*)d_in[7];
    const float* RCb = (const float*)d_in[8];
    float* out = (float*)d_out;

    dim3 pg(256, 8);
    proj_kernel<<<pg, NTHR>>>(x, WHw, WHb, 0);
    proj_kernel<<<pg, NTHR>>>(x, WCw, WCb, 1);
    rhn_seq_kernel<<<NCTA, NTHR>>>(RHw, RHb, RCw, RCb, out);
}

// round 12
// speedup vs baseline: 2.1421x; 1.3336x over previous
#include <cuda_runtime.h>
#include <math.h>

#define T_LEN 512
#define B_SZ  64
#define D_SZ  1024
#define H_SZ  512
#define L_SZ  5

#define NCTA 128
#define NTHR 256

// ---------------- device-global scratch ----------------------------------------
__device__ float    g_XHt[T_LEN * H_SZ * B_SZ];     // [t][j][b]
__device__ float    g_XCt[T_LEN * H_SZ * B_SZ];     // [t][j][b]
__device__ float    g_hr[4][4][128][64];            // h ring [par][copy kg][row][b]
__device__ float    g_pr[2][2][4][H_SZ][B_SZ];      // partials [par][gate][kg][j][b]
__device__ unsigned g_fA[NCTA];                     // phase-A done flags (monotonic)
__device__ unsigned g_fB[NCTA];                     // h-contribution flags (monotonic)

// zero h(0) (ring slot 0) each launch; kernel boundary gives visibility
__global__ void init_kernel() {
    int idx = blockIdx.x * 256 + threadIdx.x;       // 32 blocks x 256 = 8192 float4
    ((float4*)&g_hr[0][0][0][0])[idx] = make_float4(0.f, 0.f, 0.f, 0.f);
}

// ---------------- precompute: XHt/XCt[t][j][b] = x[t,b,:]@W[:,j] + bias[j] ------
__global__ void __launch_bounds__(NTHR) proj_kernel(
    const float* __restrict__ x,
    const float* __restrict__ Ww,
    const float* __restrict__ Wb,
    const int gate)
{
    __shared__ float As[32][128];
    __shared__ float Bs[32][64];
    float* __restrict__ dst = gate ? g_XCt : g_XHt;

    const int tid = threadIdx.x;
    const int bm  = blockIdx.x * 128;
    const int bn  = blockIdx.y * 64;
    const int tm  = tid & 15;
    const int tn  = tid >> 4;

    float acc[8][4];
#pragma unroll
    for (int i = 0; i < 8; i++)
#pragma unroll
        for (int j = 0; j < 4; j++) acc[i][j] = 0.0f;

    for (int k0 = 0; k0 < D_SZ; k0 += 32) {
#pragma unroll
        for (int r = 0; r < 4; r++) {
            int lin = tid + r * 256;
            int m = lin >> 3, kq = lin & 7;
            float4 v = *(const float4*)(x + (size_t)(bm + m) * D_SZ + k0 + kq * 4);
            As[kq * 4 + 0][m] = v.x;
            As[kq * 4 + 1][m] = v.y;
            As[kq * 4 + 2][m] = v.z;
            As[kq * 4 + 3][m] = v.w;
        }
#pragma unroll
        for (int r = 0; r < 2; r++) {
            int lin = tid + r * 256;
            int kk = lin >> 4, jq = lin & 15;
            *(float4*)&Bs[kk][jq * 4] =
                *(const float4*)(Ww + (size_t)(k0 + kk) * H_SZ + bn + jq * 4);
        }
        __syncthreads();
#pragma unroll
        for (int k = 0; k < 32; k++) {
            float4 a0 = *(const float4*)&As[k][tm * 4];
            float4 a1 = *(const float4*)&As[k][64 + tm * 4];
            float4 bv = *(const float4*)&Bs[k][tn * 4];
            float av[8] = {a0.x, a0.y, a0.z, a0.w, a1.x, a1.y, a1.z, a1.w};
            float bw[4] = {bv.x, bv.y, bv.z, bv.w};
#pragma unroll
            for (int i = 0; i < 8; i++)
#pragma unroll
                for (int j = 0; j < 4; j++)
                    acc[i][j] = fmaf(av[i], bw[j], acc[i][j]);
        }
        __syncthreads();
    }

#pragma unroll
    for (int i = 0; i < 8; i++) {
        int m = bm + ((i < 4) ? (tm * 4 + i) : (64 + tm * 4 + i - 4));
        int t = m >> 6, b = m & 63;
#pragma unroll
        for (int j = 0; j < 4; j++) {
            int jj = bn + tn * 4 + j;
            dst[(size_t)t * (H_SZ * B_SZ) + (size_t)jj * B_SZ + b] = acc[i][j] + Wb[jj];
        }
    }
}

// ---------------- persistent dataflow kernel: NO grid barriers ------------------
// CTA (jg,kg): jg = cta>>2 (32 groups of 16 j), kg = cta&3 (128-k quarter).
// Phase A (R2 inner loop): waits fB[32kg..32kg+31] >= n  (h(n) copy kg ready),
//   computes partials, publishes fA[cta] = n+1.
// Phase B: waits fA[jg*4 .. +3] >= n+1 (its 4 kg-peers), reduces partials for
//   its 4 j-rows, highway combine (hold in register), writes h(n+1) rows into
//   copy jg>>3 of ring slot (n+1)&3, publishes fB[cta] = n+1.
// Ring depths (h:4, partials:2) are safe by dependency-cone coverage.
__global__ void __launch_bounds__(NTHR, 1) rhn_seq_kernel(
    const float* __restrict__ RHw, const float* __restrict__ RHb,
    const float* __restrict__ RCw, const float* __restrict__ RCb,
    float* __restrict__ out)
{
    const int tid  = threadIdx.x;
    const int cta  = blockIdx.x;
    const int jg   = cta >> 2;
    const int kg   = cta & 3;
    const int j0   = jg * 16;
    const int k0   = kg * 128;
    const int lane = tid & 31;
    const int warp = tid >> 5;

    __shared__ float hs[32][64];      // [k][b] chunk of hidden
    __shared__ float rhs_s[32][16];   // [k][j] chunk of R_H
    __shared__ float rcs_s[32][16];   // [k][j] chunk of R_C

    // launch-base of the monotonic flags (all equal across CTAs at launch start)
    const unsigned baseA = *(volatile unsigned*)&g_fA[cta];
    const unsigned baseB = *(volatile unsigned*)&g_fB[cta];

    // phase-A mappings (R2)
    const int jx  = tid & 15;
    const int byq = tid >> 4;
    const int kk_r = tid >> 3, jq_r = tid & 7;

    // phase-B mapping: this CTA owns 4 j-rows of its jg slice
    const int jB    = j0 + kg * 4 + (tid >> 6);   // global j
    const int bB    = tid & 63;
    const int c_own = jg >> 3;                    // h copy receiving our rows
    const int r_own = jB - 128 * c_own;

    float hold = 0.0f;                            // h(n)[jB][bB], register-carried

    float bHr[L_SZ], bCr[L_SZ];
#pragma unroll
    for (int l = 0; l < L_SZ; l++) {
        bHr[l] = RHb[l * H_SZ + jB];
        bCr[l] = RCb[l * H_SZ + jB];
    }

    int n = 0;
    for (int pass = 0; pass < 2; pass++)
    for (int t = 0; t < T_LEN; t++)
#pragma unroll
    for (int l = 0; l < L_SZ; l++, n++) {
        const float* __restrict__ Rh = RHw + (size_t)l * H_SZ * H_SZ;
        const float* __restrict__ Rc = RCw + (size_t)l * H_SZ * H_SZ;
        const int pp = n & 1;

        // ---- wait: h(n) copy kg ready (32 producers, contiguous flags) ----
        if (warp == 0) {
            volatile unsigned* f = &g_fB[32 * kg + lane];
            const unsigned tgt = baseB + (unsigned)n;
            while ((int)(*f - tgt) < 0) { }
        }
        __syncthreads();

        const float* __restrict__ hp = &g_hr[n & 3][kg][0][0];   // 128x64

        float aH0 = 0, aH1 = 0, aH2 = 0, aH3 = 0;
        float aC0 = 0, aC1 = 0, aC2 = 0, aC3 = 0;

        // prefetch chunk 0 (h via L2; weights plain)
        float4 h0v, h1v;
        float2 r0v, r1v;
        {
            h0v = __ldcg((const float4*)hp + tid);
            h1v = __ldcg((const float4*)hp + tid + 256);
            r0v = *(const float2*)(Rh + (size_t)(k0 + kk_r) * H_SZ + j0 + 2 * jq_r);
            r1v = *(const float2*)(Rc + (size_t)(k0 + kk_r) * H_SZ + j0 + 2 * jq_r);
        }
#pragma unroll
        for (int c = 0; c < 4; c++) {
            __syncthreads();
            ((float4*)hs)[tid]       = h0v;
            ((float4*)hs)[tid + 256] = h1v;
            ((float2*)rhs_s)[tid]    = r0v;
            ((float2*)rcs_s)[tid]    = r1v;
            __syncthreads();
            if (c < 3) {
                const int off = (c + 1) * 32;                 // local rows
                h0v = __ldcg((const float4*)(hp + off * 64) + tid);
                h1v = __ldcg((const float4*)(hp + off * 64) + tid + 256);
                r0v = *(const float2*)(Rh + (size_t)(k0 + off + kk_r) * H_SZ + j0 + 2 * jq_r);
                r1v = *(const float2*)(Rc + (size_t)(k0 + off + kk_r) * H_SZ + j0 + 2 * jq_r);
            }
#pragma unroll
            for (int kk = 0; kk < 32; kk++) {
                float rh = rhs_s[kk][jx];
                float rc = rcs_s[kk][jx];
                float4 hv = *(const float4*)&hs[kk][byq * 4];
                aH0 = fmaf(hv.x, rh, aH0); aH1 = fmaf(hv.y, rh, aH1);
                aH2 = fmaf(hv.z, rh, aH2); aH3 = fmaf(hv.w, rh, aH3);
                aC0 = fmaf(hv.x, rc, aC0); aC1 = fmaf(hv.y, rc, aC1);
                aC2 = fmaf(hv.z, rc, aC2); aC3 = fmaf(hv.w, rc, aC3);
            }
        }
        __stcg((float4*)&g_pr[pp][0][kg][j0 + jx][byq * 4],
               make_float4(aH0, aH1, aH2, aH3));
        __stcg((float4*)&g_pr[pp][1][kg][j0 + jx][byq * 4],
               make_float4(aC0, aC1, aC2, aC3));
        __syncthreads();
        if (tid == 0) {
            __threadfence();
            atomicExch(&g_fA[cta], baseA + (unsigned)n + 1u);
        }

        // ---- wait: 4 kg-peers' partials ready ----
        if (warp == 0 && lane < 4) {
            volatile unsigned* f = &g_fA[jg * 4 + lane];
            const unsigned tgt = baseA + (unsigned)n + 1u;
            while ((int)(*f - tgt) < 0) { }
        }
        __syncthreads();

        // ---- phase B: reduce + activations + highway combine ----
        {
            float sH = __ldcg(&g_pr[pp][0][0][jB][bB]) + __ldcg(&g_pr[pp][0][1][jB][bB])
                     + __ldcg(&g_pr[pp][0][2][jB][bB]) + __ldcg(&g_pr[pp][0][3][jB][bB]);
            float sC = __ldcg(&g_pr[pp][1][0][jB][bB]) + __ldcg(&g_pr[pp][1][1][jB][bB])
                     + __ldcg(&g_pr[pp][1][2][jB][bB]) + __ldcg(&g_pr[pp][1][3][jB][bB]);
            sH += bHr[l];
            sC += bCr[l];
            if (l == 0) {
                sH += __ldcg(&g_XHt[(size_t)t * (H_SZ * B_SZ) + (size_t)jB * B_SZ + bB]);
                sC += __ldcg(&g_XCt[(size_t)t * (H_SZ * B_SZ) + (size_t)jB * B_SZ + bB]);
            }
            float hl = 1.0f - 2.0f / (1.0f + __expf(2.0f * sH));   // tanh
            float tl = 1.0f / (1.0f + __expf(-sC));                // sigmoid
            float hn = fmaf(tl, hl - hold, hold);
            hold = hn;
            __stcg(&g_hr[(n + 1) & 3][c_own][r_own][bB], hn);
            if (l == L_SZ - 1) {
                size_t o = (size_t)t * (B_SZ * 2 * H_SZ) + (size_t)bB * (2 * H_SZ)
                         + (size_t)pass * H_SZ + jB;
                out[o] = hn;
                if (t == T_LEN - 1) {
                    out[(size_t)T_LEN * (B_SZ * 2 * H_SZ) + (size_t)bB * (2 * H_SZ)
                        + (size_t)pass * H_SZ + jB] = hn;
                }
            }
        }
        __syncthreads();
        if (tid == 0) {
            __threadfence();
            atomicExch(&g_fB[cta], baseB + (unsigned)n + 1u);
        }
    }
}

extern "C" void kernel_launch(void* const* d_in, const int* in_sizes, int n_in,
                              void* d_out, int out_size)
{
    const float* x   = (const float*)d_in[0];
    const float* WHw = (const float*)d_in[1];
    const float* WHb = (const float*)d_in[2];
    const float* WCw = (const float*)d_in[3];
    const float* WCb = (const float*)d_in[4];
    const float* RHw = (const float*)d_in[5];
    const float* RHb = (const float*)d_in[6];
    const float* RCw = (const float*)d_in[7];
    const float* RCb = (const float*)d_in[8];
    float* out = (float*)d_out;

    init_kernel<<<32, 256>>>();
    dim3 pg(256, 8);
    proj_kernel<<<pg, NTHR>>>(x, WHw, WHb, 0);
    proj_kernel<<<pg, NTHR>>>(x, WCw, WCb, 1);
    rhn_seq_kernel<<<NCTA, NTHR>>>(RHw, RHb, RCw, RCb, out);
}